// round 5
// baseline (speedup 1.0000x reference)
#include <cuda_runtime.h>

#define NROWS 16384
#define K 128
#define D 64
#define RPB 8
#define NBLOCKS (NROWS / RPB)
#define TPB 256
#define LOG2E 1.4426950408889634f

typedef unsigned long long u64;

__device__ __forceinline__ u64 f2add(u64 a, u64 b) {
    u64 r; asm("add.rn.f32x2 %0, %1, %2;" : "=l"(r) : "l"(a), "l"(b)); return r;
}
__device__ __forceinline__ u64 f2mul(u64 a, u64 b) {
    u64 r; asm("mul.rn.f32x2 %0, %1, %2;" : "=l"(r) : "l"(a), "l"(b)); return r;
}
__device__ __forceinline__ u64 f2fma(u64 a, u64 b, u64 c) {
    u64 r; asm("fma.rn.f32x2 %0, %1, %2, %3;" : "=l"(r) : "l"(a), "l"(b), "l"(c)); return r;
}
__device__ __forceinline__ u64 fpack(float lo, float hi) {
    u64 r; asm("mov.b64 %0, {%1, %2};" : "=l"(r) : "f"(lo), "f"(hi)); return r;
}
__device__ __forceinline__ void funpack(u64 v, float& lo, float& hi) {
    asm("mov.b64 {%0, %1}, %2;" : "=f"(lo), "=f"(hi) : "l"(v));
}
__device__ __forceinline__ float frcp(float x) {
    float r; asm("rcp.approx.f32 %0, %1;" : "=f"(r) : "f"(x)); return r;
}
__device__ __forceinline__ float fex2(float x) {
    float r; asm("ex2.approx.f32 %0, %1;" : "=f"(r) : "f"(x)); return r;
}
__device__ __forceinline__ float fsqrt_(float x) {
    float r; asm("sqrt.approx.f32 %0, %1;" : "=f"(r) : "f"(x)); return r;
}

// loss = mean_{n,k} exp(-(rank_k-1)/8) * d_k
// rank_k-1 = (sum_all_j a/(a+a_j)) - 0.5,  a = exp(5d-20)
// group-of-4 RCP batching, two column groups per f32x2 lane pair.
// Thread pair (2k, 2k+1) co-owns centroid k: half the weights, half the rank loop.

__global__ __launch_bounds__(TPB, 4) void dng_kernel(const float* __restrict__ data,
                                                     const float* __restrict__ weights,
                                                     float* __restrict__ out)
{
    // half-regions padded by 16B so the two concurrent broadcast groups hit disjoint banks
    __shared__ __align__(16) float x_s[68];    // [0..31] half0, pad4, [36..67] half1
    __shared__ __align__(16) float saq[132];   // [0..63] half0, pad4, [68..131] half1
    __shared__ float x2_s[2];
    __shared__ float warp_sums[TPB / 32];

    const int t = threadIdx.x;
    const int kc = t >> 1;      // centroid 0..127
    const int half = t & 1;     // which half of dims / rank range
    const int lane = t & 31;
    const int wid = t >> 5;

    // this thread's 32 dims of centroid kc: packed -2*w, partial |w|^2
    u64 wv[16];
    float cpart = 0.0f;
    {
        const float4* wp = (const float4*)(weights + kc * D + half * 32);
#pragma unroll
        for (int i = 0; i < 8; i++) {
            float4 v = wp[i];
            cpart = fmaf(v.x, v.x, cpart); cpart = fmaf(v.y, v.y, cpart);
            cpart = fmaf(v.z, v.z, cpart); cpart = fmaf(v.w, v.w, cpart);
            wv[2 * i]     = fpack(-2.0f * v.x, -2.0f * v.y);
            wv[2 * i + 1] = fpack(-2.0f * v.z, -2.0f * v.w);
        }
    }

    // per-half smem views (both offsets are 16B-aligned: 36*4=144, 68*4=272)
    const ulonglong2* xv  = (const ulonglong2*)(x_s + half * 36);
    const ulonglong2* sav = (const ulonglong2*)(saq + half * 68);

    // store slot for a_kc (interleaved pairs (a_j, a_{j+64}), split across padded halves)
    const int jm  = kc & 63;
    const int hi  = kc >> 6;
    const int reg = (jm >= 32);
    const int slot = reg * 68 + 2 * (jm - reg * 32) + hi;

    float acc = 0.0f;
    const int row0 = blockIdx.x * RPB;

    for (int r = 0; r < RPB; r++) {
        // stage data row (padded) + |x|^2 via warps 0,1
        if (t < D) {
            float v = data[(row0 + r) * D + t];
            x_s[t + (t >= 32 ? 4 : 0)] = v;
            float p = v * v;
#pragma unroll
            for (int o = 16; o; o >>= 1) p += __shfl_down_sync(0xFFFFFFFFu, p, o);
            if (lane == 0) x2_s[wid] = p;
        }
        __syncthreads();   // x ready; fences prior-iter saq reads

        // partial dot over this thread's 32 dims
        u64 dv0 = 0ull, dv1 = 0ull;
#pragma unroll
        for (int i = 0; i < 8; i++) {
            ulonglong2 q = xv[i];
            dv0 = f2fma(q.x, wv[2 * i],     dv0);
            dv1 = f2fma(q.y, wv[2 * i + 1], dv1);
        }
        float e0, e1, e2, e3;
        funpack(dv0, e0, e1); funpack(dv1, e2, e3);
        float d2p = cpart + ((e0 + e1) + (e2 + e3));
        float d2 = (x2_s[0] + x2_s[1]) + d2p + __shfl_xor_sync(0xFFFFFFFFu, d2p, 1);
        float dist = fsqrt_(fmaxf(d2, 0.0f));
        float a = fex2(fmaf(dist, 5.0f * LOG2E, -20.0f * LOG2E));

        if (half == 0) saq[slot] = a;
        __syncthreads();   // saq ready

        // half of the rank loop: 8 iters x (4 j's per lane x 2 lanes)
        const u64 av = fpack(a, a);
        u64 qv = 0ull;
#pragma unroll
        for (int jj = 0; jj < 8; jj++) {
            ulonglong2 b12 = sav[2 * jj];
            ulonglong2 b34 = sav[2 * jj + 1];
            u64 tv1 = f2add(av, b12.x), tv2 = f2add(av, b12.y);
            u64 tv3 = f2add(av, b34.x), tv4 = f2add(av, b34.y);
            u64 p12 = f2mul(tv1, tv2), p34 = f2mul(tv3, tv4);
            u64 s12 = f2add(tv1, tv2), s34 = f2add(tv3, tv4);
            u64 Nv  = f2fma(p34, s12, f2mul(p12, s34));
            u64 pv  = f2mul(p12, p34);
            float pA, pB; funpack(pv, pA, pB);
            qv = f2fma(Nv, fpack(frcp(pA), frcp(pB)), qv);
        }
        float qA, qB; funpack(qv, qA, qB);
        float spart = qA + qB;
        float s = a * (spart + __shfl_xor_sync(0xFFFFFFFFu, spart, 1));
        float rank_m1 = s - 0.5f;
        // both threads of the pair add the same term; final scale has a 0.5 factor
        acc = fmaf(fex2(-rank_m1 * (0.125f * LOG2E)), dist, acc);
        __syncthreads();   // saq reads done before next row overwrites
    }

    // block reduction -> global atomic
#pragma unroll
    for (int o = 16; o; o >>= 1) acc += __shfl_down_sync(0xFFFFFFFFu, acc, o);
    if (lane == 0) warp_sums[wid] = acc;
    __syncthreads();
    if (t == 0) {
        float tot = 0.0f;
#pragma unroll
        for (int i = 0; i < TPB / 32; i++) tot += warp_sums[i];
        atomicAdd(out, tot * (0.5f / ((float)NROWS * (float)K)));
    }
}

extern "C" void kernel_launch(void* const* d_in, const int* in_sizes, int n_in,
                              void* d_out, int out_size)
{
    const float* data    = (const float*)d_in[0];
    const float* weights = (const float*)d_in[1];
    float* out = (float*)d_out;

    cudaMemsetAsync(out, 0, sizeof(float));
    dng_kernel<<<NBLOCKS, TPB>>>(data, weights, out);
}

// round 7
// speedup vs baseline: 1.0682x; 1.0682x over previous
#include <cuda_runtime.h>

#define NROWS 16384
#define K 128
#define D 64
#define RPB 8
#define NBLOCKS (NROWS / RPB)
#define LOG2E 1.4426950408889634f

typedef unsigned long long u64;

__device__ __forceinline__ u64 f2add(u64 a, u64 b) {
    u64 r; asm("add.rn.f32x2 %0, %1, %2;" : "=l"(r) : "l"(a), "l"(b)); return r;
}
__device__ __forceinline__ u64 f2mul(u64 a, u64 b) {
    u64 r; asm("mul.rn.f32x2 %0, %1, %2;" : "=l"(r) : "l"(a), "l"(b)); return r;
}
__device__ __forceinline__ u64 f2fma(u64 a, u64 b, u64 c) {
    u64 r; asm("fma.rn.f32x2 %0, %1, %2, %3;" : "=l"(r) : "l"(a), "l"(b), "l"(c)); return r;
}
__device__ __forceinline__ u64 fpack(float lo, float hi) {
    u64 r; asm("mov.b64 %0, {%1, %2};" : "=l"(r) : "f"(lo), "f"(hi)); return r;
}
__device__ __forceinline__ void funpack(u64 v, float& lo, float& hi) {
    asm("mov.b64 {%0, %1}, %2;" : "=f"(lo), "=f"(hi) : "l"(v));
}
__device__ __forceinline__ float frcp(float x) {
    float r; asm("rcp.approx.f32 %0, %1;" : "=f"(r) : "f"(x)); return r;
}
__device__ __forceinline__ float fex2(float x) {
    float r; asm("ex2.approx.f32 %0, %1;" : "=f"(r) : "f"(x)); return r;
}
__device__ __forceinline__ float fsqrt_(float x) {
    float r; asm("sqrt.approx.f32 %0, %1;" : "=f"(r) : "f"(x)); return r;
}

// loss = mean_{n,k} exp(-(rank_k-1)/8) * d_k
// rank_k-1 = (sum_all_j a/(a+a_j)) - 0.5,  a = exp(5d-20) (rescaled; ratios invariant)
// group-of-4 RCP batching; two column groups (j | j+64) per f32x2 lane pair.
// Structure: stage 8 rows -> sync -> 8 dots -> sync -> 4x two-row rank loops (no syncs).

__global__ __launch_bounds__(128) void dng_kernel(const float* __restrict__ data,
                                                  const float* __restrict__ weights,
                                                  float* __restrict__ out)
{
    __shared__ ulonglong2 x_v[RPB][D / 4];     // 8 staged rows, 256B each (float alias)
    __shared__ ulonglong2 sa_v[RPB][K / 4];    // per-row interleaved (a_j, a_{j+64}) pairs
    __shared__ float x2_s[RPB];
    __shared__ float warp_sums[4];

    float* x_s = (float*)x_v;
    float* saq = (float*)sa_v;

    const int k = threadIdx.x;
    const int lane = k & 31;
    const int wid = k >> 5;

    // weights row k: packed -2*w pairs + c = |w|^2  (wv[i] = dims 2i, 2i+1)
    u64 wv[D / 2];
    float c = 0.0f;
    {
        const float4* wp = (const float4*)(weights + k * D);
#pragma unroll
        for (int i = 0; i < D / 4; i++) {
            float4 v = wp[i];
            c = fmaf(v.x, v.x, c); c = fmaf(v.y, v.y, c);
            c = fmaf(v.z, v.z, c); c = fmaf(v.w, v.w, c);
            wv[2 * i]     = fpack(-2.0f * v.x, -2.0f * v.y);
            wv[2 * i + 1] = fpack(-2.0f * v.z, -2.0f * v.w);
        }
    }

    // ---- phase 1: stage all 8 rows + per-row |x|^2 (one sync) ----
    {
        // thread k loads float4 #k: 16 float4 per row -> row = k>>4
        float4 v = ((const float4*)(data + blockIdx.x * RPB * D))[k];
        ((float4*)x_s)[k] = v;
        float p = fmaf(v.x, v.x, fmaf(v.y, v.y, fmaf(v.z, v.z, v.w * v.w)));
#pragma unroll
        for (int o = 8; o; o >>= 1) p += __shfl_down_sync(0xFFFFFFFFu, p, o, 16);
        if ((k & 15) == 0) x2_s[k >> 4] = p;
    }
    __syncthreads();

    // ---- phase 2: 8 independent dots -> dist[r]; store a to smem (one sync) ----
    const int jm = k & 63, hi = k >> 6;
    const int slot = 2 * jm + hi;              // interleaved pair slot within a row
    float dist[RPB];
#pragma unroll
    for (int r = 0; r < RPB; r++) {
        u64 dv0 = 0ull, dv1 = 0ull;
        const u64* xw = (const u64*)x_v[r];    // 32 u64 words = 64 floats
#pragma unroll
        for (int i = 0; i < D / 2; i++) {
            u64 xq = xw[i];                    // LDS broadcast
            if (i & 1) dv1 = f2fma(xq, wv[i], dv1);
            else       dv0 = f2fma(xq, wv[i], dv0);
        }
        float e0, e1, e2, e3;
        funpack(dv0, e0, e1); funpack(dv1, e2, e3);
        float d2 = ((e0 + e1) + (e2 + e3)) + (c + x2_s[r]);
        float dd = fsqrt_(fmaxf(d2, 0.0f));
        dist[r] = dd;
        saq[r * K + slot] = fex2(fmaf(dd, 5.0f * LOG2E, -20.0f * LOG2E));
    }
    __syncthreads();

    // ---- phase 3: rank loops, two rows interleaved per pass, no syncs ----
    float acc = 0.0f;
#pragma unroll
    for (int rp = 0; rp < RPB / 2; rp++) {
        const int r0 = 2 * rp, r1 = 2 * rp + 1;
        float a0 = fex2(fmaf(dist[r0], 5.0f * LOG2E, -20.0f * LOG2E));
        float a1 = fex2(fmaf(dist[r1], 5.0f * LOG2E, -20.0f * LOG2E));
        const u64 av0 = fpack(a0, a0), av1 = fpack(a1, a1);
        u64 qv0 = 0ull, qv1 = 0ull;
#pragma unroll
        for (int jj = 0; jj < 16; jj++) {
            ulonglong2 b12 = sa_v[r0][2 * jj];
            ulonglong2 b34 = sa_v[r0][2 * jj + 1];
            ulonglong2 c12 = sa_v[r1][2 * jj];
            ulonglong2 c34 = sa_v[r1][2 * jj + 1];
            {   // row r0 pipeline
                u64 t1 = f2add(av0, b12.x), t2 = f2add(av0, b12.y);
                u64 t3 = f2add(av0, b34.x), t4 = f2add(av0, b34.y);
                u64 p12 = f2mul(t1, t2), p34 = f2mul(t3, t4);
                u64 s12 = f2add(t1, t2), s34 = f2add(t3, t4);
                u64 Nv  = f2fma(p34, s12, f2mul(p12, s34));
                u64 pv  = f2mul(p12, p34);
                float pA, pB; funpack(pv, pA, pB);
                qv0 = f2fma(Nv, fpack(frcp(pA), frcp(pB)), qv0);
            }
            {   // row r1 pipeline (independent chain)
                u64 t1 = f2add(av1, c12.x), t2 = f2add(av1, c12.y);
                u64 t3 = f2add(av1, c34.x), t4 = f2add(av1, c34.y);
                u64 p12 = f2mul(t1, t2), p34 = f2mul(t3, t4);
                u64 s12 = f2add(t1, t2), s34 = f2add(t3, t4);
                u64 Nv  = f2fma(p34, s12, f2mul(p12, s34));
                u64 pv  = f2mul(p12, p34);
                float pA, pB; funpack(pv, pA, pB);
                qv1 = f2fma(Nv, fpack(frcp(pA), frcp(pB)), qv1);
            }
        }
        float qA, qB, qC, qD;
        funpack(qv0, qA, qB); funpack(qv1, qC, qD);
        float rk0 = a0 * (qA + qB) - 0.5f;
        float rk1 = a1 * (qC + qD) - 0.5f;
        acc = fmaf(fex2(-rk0 * (0.125f * LOG2E)), dist[r0], acc);
        acc = fmaf(fex2(-rk1 * (0.125f * LOG2E)), dist[r1], acc);
    }

    // ---- block reduction -> global atomic ----
#pragma unroll
    for (int o = 16; o; o >>= 1) acc += __shfl_down_sync(0xFFFFFFFFu, acc, o);
    if (lane == 0) warp_sums[wid] = acc;
    __syncthreads();
    if (k == 0) {
        float t = warp_sums[0] + warp_sums[1] + warp_sums[2] + warp_sums[3];
        atomicAdd(out, t * (1.0f / ((float)NROWS * (float)K)));
    }
}

extern "C" void kernel_launch(void* const* d_in, const int* in_sizes, int n_in,
                              void* d_out, int out_size)
{
    const float* data    = (const float*)d_in[0];
    const float* weights = (const float*)d_in[1];
    float* out = (float*)d_out;

    cudaMemsetAsync(out, 0, sizeof(float));
    dng_kernel<<<NBLOCKS, 128>>>(data, weights, out);
}

// round 8
// speedup vs baseline: 1.1119x; 1.0409x over previous
#include <cuda_runtime.h>

#define NROWS 16384
#define K 128
#define D 64
#define RPB 8
#define NBLOCKS (NROWS / RPB)
#define LOG2E 1.4426950408889634f

typedef unsigned long long u64;

__device__ __forceinline__ u64 f2add(u64 a, u64 b) {
    u64 r; asm("add.rn.f32x2 %0, %1, %2;" : "=l"(r) : "l"(a), "l"(b)); return r;
}
__device__ __forceinline__ u64 f2mul(u64 a, u64 b) {
    u64 r; asm("mul.rn.f32x2 %0, %1, %2;" : "=l"(r) : "l"(a), "l"(b)); return r;
}
__device__ __forceinline__ u64 f2fma(u64 a, u64 b, u64 c) {
    u64 r; asm("fma.rn.f32x2 %0, %1, %2, %3;" : "=l"(r) : "l"(a), "l"(b), "l"(c)); return r;
}
__device__ __forceinline__ u64 fpack(float lo, float hi) {
    u64 r; asm("mov.b64 %0, {%1, %2};" : "=l"(r) : "f"(lo), "f"(hi)); return r;
}
__device__ __forceinline__ void funpack(u64 v, float& lo, float& hi) {
    asm("mov.b64 {%0, %1}, %2;" : "=f"(lo), "=f"(hi) : "l"(v));
}
__device__ __forceinline__ float frcp(float x) {
    float r; asm("rcp.approx.f32 %0, %1;" : "=f"(r) : "f"(x)); return r;
}
__device__ __forceinline__ float fex2(float x) {
    float r; asm("ex2.approx.f32 %0, %1;" : "=f"(r) : "f"(x)); return r;
}
__device__ __forceinline__ float fsqrt_(float x) {
    float r; asm("sqrt.approx.f32 %0, %1;" : "=f"(r) : "f"(x)); return r;
}

// loss = mean_{n,k} exp(-(rank_k-1)/8) * d_k
// rank_k-1 = (sum_all_j a/(a+a_j)) - 0.5,  a = exp(5d-20)
// Per group of 4 j's with symmetric polys e1..e4 of (b1..b4):
//   P(a) = prod(a+b_i) = ((a+e1)a+e2)a+e3)a+e4   (Horner partials h1,h2,h3)
//   N(a) = P'(a) = sum_i prod_{j!=i}(a+b_j)      (derivative chain on h's)
//   sum_i a/(a+b_i) = a * N / P  -> one RCP per 4 pairs
// e1..e4 are thread-invariant per (row, group): precomputed cooperatively.
// Two column groups (j | j+64) per f32x2 lane pair.

__global__ __launch_bounds__(128) void dng_kernel(const float* __restrict__ data,
                                                  const float* __restrict__ weights,
                                                  float* __restrict__ out)
{
    __shared__ ulonglong2 x_v[RPB][D / 4];       // 8 rows x 256B (float alias)
    __shared__ ulonglong2 sa_v[RPB][K / 4];      // per-row interleaved (a_j, a_{j+64}) pairs
    __shared__ ulonglong2 e_v[RPB][16][2];       // per (row, jj): {e1,e2},{e3,e4} packed AB lanes
    __shared__ float x2_s[RPB];
    __shared__ float warp_sums[4];

    float* x_s = (float*)x_v;
    float* saq = (float*)sa_v;

    const int k = threadIdx.x;
    const int lane = k & 31;
    const int wid = k >> 5;

    // weights row k: packed -2*w pairs + c = |w|^2  (wv[i] = dims 2i, 2i+1)
    u64 wv[D / 2];
    float c = 0.0f;
    {
        const float4* wp = (const float4*)(weights + k * D);
#pragma unroll
        for (int i = 0; i < D / 4; i++) {
            float4 v = wp[i];
            c = fmaf(v.x, v.x, c); c = fmaf(v.y, v.y, c);
            c = fmaf(v.z, v.z, c); c = fmaf(v.w, v.w, c);
            wv[2 * i]     = fpack(-2.0f * v.x, -2.0f * v.y);
            wv[2 * i + 1] = fpack(-2.0f * v.z, -2.0f * v.w);
        }
    }

    // ---- phase 1: stage 8 rows + per-row |x|^2 ----
    {
        float4 v = ((const float4*)(data + blockIdx.x * RPB * D))[k];   // row = k>>4
        ((float4*)x_s)[k] = v;
        float p = fmaf(v.x, v.x, fmaf(v.y, v.y, fmaf(v.z, v.z, v.w * v.w)));
#pragma unroll
        for (int o = 8; o; o >>= 1) p += __shfl_down_sync(0xFFFFFFFFu, p, o, 16);
        if ((k & 15) == 0) x2_s[k >> 4] = p;
    }
    __syncthreads();

    // ---- phase 2: 8 independent dots -> dist[r]; a -> smem ----
    const int jm = k & 63, hi = k >> 6;
    const int slot = 2 * jm + hi;                // u64 word jm holds (a_jm, a_{jm+64})
    float dist[RPB];
#pragma unroll
    for (int r = 0; r < RPB; r++) {
        u64 dv0 = 0ull, dv1 = 0ull;
#pragma unroll
        for (int i = 0; i < D / 4; i++) {        // 16 x LDS.128 broadcast
            ulonglong2 q = x_v[r][i];
            dv0 = f2fma(q.x, wv[2 * i],     dv0);
            dv1 = f2fma(q.y, wv[2 * i + 1], dv1);
        }
        float e0, e1, e2, e3;
        funpack(dv0, e0, e1); funpack(dv1, e2, e3);
        float d2 = ((e0 + e1) + (e2 + e3)) + (c + x2_s[r]);
        float dd = fsqrt_(fmaxf(d2, 0.0f));
        dist[r] = dd;
        saq[r * K + slot] = fex2(fmaf(dd, 5.0f * LOG2E, -20.0f * LOG2E));
    }
    __syncthreads();

    // ---- phase 2.5: symmetric polys, one (row, jj) task per thread ----
    {
        const int r = k >> 4, jj = k & 15;
        const ulonglong2* src = (const ulonglong2*)(saq + r * K + 8 * jj);
        ulonglong2 w0 = src[0];                  // b1v, b2v  (lanes = groups j / j+64)
        ulonglong2 w1 = src[1];                  // b3v, b4v
        u64 s12 = f2add(w0.x, w0.y), p12 = f2mul(w0.x, w0.y);
        u64 s34 = f2add(w1.x, w1.y), p34 = f2mul(w1.x, w1.y);
        u64 e1 = f2add(s12, s34);
        u64 e2 = f2fma(s12, s34, f2add(p12, p34));
        u64 e3 = f2fma(p12, s34, f2mul(p34, s12));
        u64 e4 = f2mul(p12, p34);
        e_v[r][jj][0] = make_ulonglong2(e1, e2);
        e_v[r][jj][1] = make_ulonglong2(e3, e4);
    }
    __syncthreads();

    // ---- phase 3: rank loops, two rows interleaved, no syncs ----
    float acc = 0.0f;
#pragma unroll
    for (int rp = 0; rp < RPB / 2; rp++) {
        const int r0 = 2 * rp, r1 = 2 * rp + 1;
        float a0 = fex2(fmaf(dist[r0], 5.0f * LOG2E, -20.0f * LOG2E));
        float a1 = fex2(fmaf(dist[r1], 5.0f * LOG2E, -20.0f * LOG2E));
        const u64 av0 = fpack(a0, a0), av1 = fpack(a1, a1);
        u64 qv0 = 0ull, qv1 = 0ull;
#pragma unroll
        for (int jj = 0; jj < 16; jj++) {
            ulonglong2 ea0 = e_v[r0][jj][0];     // {e1, e2}  broadcast
            ulonglong2 eb0 = e_v[r0][jj][1];     // {e3, e4}
            ulonglong2 ea1 = e_v[r1][jj][0];
            ulonglong2 eb1 = e_v[r1][jj][1];
            {   // row r0: P via Horner, N via derivative chain
                u64 h1 = f2add(av0, ea0.x);
                u64 h2 = f2fma(h1, av0, ea0.y);
                u64 h3 = f2fma(h2, av0, eb0.x);
                u64 Pv = f2fma(h3, av0, eb0.y);
                u64 g2 = f2add(h1, av0);
                u64 g3 = f2fma(g2, av0, h2);
                u64 Nv = f2fma(g3, av0, h3);
                float pA, pB; funpack(Pv, pA, pB);
                qv0 = f2fma(Nv, fpack(frcp(pA), frcp(pB)), qv0);
            }
            {   // row r1 (independent chain)
                u64 h1 = f2add(av1, ea1.x);
                u64 h2 = f2fma(h1, av1, ea1.y);
                u64 h3 = f2fma(h2, av1, eb1.x);
                u64 Pv = f2fma(h3, av1, eb1.y);
                u64 g2 = f2add(h1, av1);
                u64 g3 = f2fma(g2, av1, h2);
                u64 Nv = f2fma(g3, av1, h3);
                float pA, pB; funpack(Pv, pA, pB);
                qv1 = f2fma(Nv, fpack(frcp(pA), frcp(pB)), qv1);
            }
        }
        float qA, qB, qC, qD;
        funpack(qv0, qA, qB); funpack(qv1, qC, qD);
        float rk0 = a0 * (qA + qB) - 0.5f;
        float rk1 = a1 * (qC + qD) - 0.5f;
        acc = fmaf(fex2(-rk0 * (0.125f * LOG2E)), dist[r0], acc);
        acc = fmaf(fex2(-rk1 * (0.125f * LOG2E)), dist[r1], acc);
    }

    // ---- block reduction -> global atomic ----
#pragma unroll
    for (int o = 16; o; o >>= 1) acc += __shfl_down_sync(0xFFFFFFFFu, acc, o);
    if (lane == 0) warp_sums[wid] = acc;
    __syncthreads();
    if (k == 0) {
        float t = warp_sums[0] + warp_sums[1] + warp_sums[2] + warp_sums[3];
        atomicAdd(out, t * (1.0f / ((float)NROWS * (float)K)));
    }
}

extern "C" void kernel_launch(void* const* d_in, const int* in_sizes, int n_in,
                              void* d_out, int out_size)
{
    const float* data    = (const float*)d_in[0];
    const float* weights = (const float*)d_in[1];
    float* out = (float*)d_out;

    cudaMemsetAsync(out, 0, sizeof(float));
    dng_kernel<<<NBLOCKS, 128>>>(data, weights, out);
}